// round 4
// baseline (speedup 1.0000x reference)
#include <cuda_runtime.h>
#include <cuda_bf16.h>
#include <math.h>

// ---------------------------------------------------------------------------
// DVDMixer: B = 32*128 = 4096 rows
// N_AGENTS=16, RNN_H=64, N_HEADS=4, GAT_D=32, EMB=32, SDIM=128
// ---------------------------------------------------------------------------

#define BROWS 4096

__device__ float g_buf[(size_t)BROWS * 4 * 16 * 32];   // 33.5 MB (L2-resident)
__device__ float epi_buf[(size_t)BROWS * 65];          // b1v | |wf| | v

// ---------------- packed fp32x2 helpers (FFMA2 — PTX-only on sm_103a) -------
typedef unsigned long long u64t;
__device__ __forceinline__ u64t pack2(float lo, float hi) {
    u64t r; asm("mov.b64 %0,{%1,%2};" : "=l"(r) : "f"(lo), "f"(hi)); return r;
}
__device__ __forceinline__ void unpack2(u64t v, float& lo, float& hi) {
    asm("mov.b64 {%0,%1},%2;" : "=f"(lo), "=f"(hi) : "l"(v));
}
__device__ __forceinline__ u64t fma2(u64t a, u64t b, u64t c) {
    u64t d; asm("fma.rn.f32x2 %0,%1,%2,%3;" : "=l"(d) : "l"(a), "l"(b), "l"(c));
    return d;
}
__device__ __forceinline__ u64t mul2(u64t a, u64t b) {
    u64t d; asm("mul.rn.f32x2 %0,%1,%2;" : "=l"(d) : "l"(a), "l"(b));
    return d;
}

// ============================= Kernel A: GAT + epilogue prep ================
// 8 rows/block (1 warp per row), 256 threads, 512 blocks, 2 CTAs/SM (128 regs).
#define GAT_SMEM_FLOATS (8192 + 2560)

__global__ __launch_bounds__(256, 2)
void gat_kernel(const float* __restrict__ hs_g,
                const float* __restrict__ Wg,
                const float* __restrict__ att,
                const float* __restrict__ s_g,
                const float* __restrict__ b1W, const float* __restrict__ b1b,
                const float* __restrict__ wfW, const float* __restrict__ wfb,
                const float* __restrict__ V1W, const float* __restrict__ V1b,
                const float* __restrict__ V2W, const float* __restrict__ V2b)
{
    extern __shared__ float sm[];
    float* shs   = sm;            // [8][16][64]
    float* sattn = sm + 8192;     // [8][16][20]

    const int tid  = threadIdx.x;
    const int lane = tid & 31;
    const int w    = tid >> 5;     // warp = local row
    const int brow = blockIdx.x * 8;

    // stage hs (coalesced float4)
    const float4* src4 = (const float4*)(hs_g + (size_t)brow * 1024);
    for (int i = tid; i < 2048; i += 256)
        ((float4*)shs)[i] = src4[i];

    // ---- epilogue prep for row (brow+w): lane = e (EMB=32) ----
    {
        const int row = brow + w;
        float ab = 0.f, aw = 0.f, av = 0.f;
        const float* srow = s_g + (size_t)row * 128;
        #pragma unroll 4
        for (int k = 0; k < 128; k++) {
            const float sv = __ldg(srow + k);
            ab += sv * __ldg(b1W + k * 32 + lane);
            aw += sv * __ldg(wfW + k * 32 + lane);
            av += sv * __ldg(V1W + k * 32 + lane);
        }
        const float b1v = ab + __ldg(b1b + lane);
        const float wfv = fabsf(aw + __ldg(wfb + lane));
        float v1 = fmaxf(av + __ldg(V1b + lane), 0.f) * __ldg(V2W + lane);
        #pragma unroll
        for (int d = 16; d; d >>= 1)
            v1 += __shfl_xor_sync(0xffffffffu, v1, d);
        epi_buf[(size_t)row * 65 + lane]      = b1v;
        epi_buf[(size_t)row * 65 + 32 + lane] = wfv;
        if (lane == 0)
            epi_buf[(size_t)row * 65 + 64] = v1 + __ldg(V2b);
    }
    __syncthreads();

    // ---- GAT per head, hp register-resident (lane = d, 32 dims) ----
    float* sat = sattn + w * 320;             // [16][20]
    const float* hsrow = shs + w * 1024;      // [16][64]

    for (int h = 0; h < 4; h++) {
        float hp[16];
        #pragma unroll
        for (int n = 0; n < 16; n++) hp[n] = 0.f;

        const float* Wcol = Wg + h * 32 + lane;
        #pragma unroll 4
        for (int kq = 0; kq < 16; kq++) {
            const float w0 = __ldg(Wcol + (4 * kq + 0) * 128);
            const float w1 = __ldg(Wcol + (4 * kq + 1) * 128);
            const float w2 = __ldg(Wcol + (4 * kq + 2) * 128);
            const float w3 = __ldg(Wcol + (4 * kq + 3) * 128);
            #pragma unroll
            for (int n = 0; n < 16; n++) {
                const float4 hv = *(const float4*)(hsrow + n * 64 + kq * 4);
                hp[n] += hv.x * w0 + hv.y * w1 + hv.z * w2 + hv.w * w3;
            }
        }

        // src/dst via butterfly reductions over d (=lanes)
        const float asrc = __ldg(att + h * 64 + lane);
        const float adst = __ldg(att + h * 64 + 32 + lane);
        float srcv[16], dstv[16];
        #pragma unroll
        for (int n = 0; n < 16; n++) {
            float ps = hp[n] * asrc, pd = hp[n] * adst;
            #pragma unroll
            for (int d = 16; d; d >>= 1) {
                ps += __shfl_xor_sync(0xffffffffu, ps, d);
                pd += __shfl_xor_sync(0xffffffffu, pd, d);
            }
            srcv[n] = ps; dstv[n] = pd;
        }

        // softmax: lane handles (i = lane&15, j in (lane>>4)*8 .. +8)
        {
            const int i  = lane & 15;
            const int jb = (lane >> 4) * 8;
            float e[8], mx = -1e30f;
            #pragma unroll
            for (int jj = 0; jj < 8; jj++) {
                float x = srcv[i] + dstv[jb + jj];
                x = x > 0.f ? x : 0.2f * x;      // leaky_relu 0.2
                e[jj] = x;
                mx = fmaxf(mx, x);
            }
            mx = fmaxf(mx, __shfl_xor_sync(0xffffffffu, mx, 16));
            float s = 0.f;
            #pragma unroll
            for (int jj = 0; jj < 8; jj++) { e[jj] = expf(e[jj] - mx); s += e[jj]; }
            s += __shfl_xor_sync(0xffffffffu, s, 16);
            const float inv = 1.f / s;
            #pragma unroll
            for (int jj = 0; jj < 8; jj++)
                sat[i * 20 + jb + jj] = e[jj] * inv;
        }
        __syncwarp();

        // g[i][d] = elu( sum_j attn[i][j] * hp[j][d] ), lane = d
        float* gbase = g_buf + (((size_t)(brow + w) * 4 + h) * 16) * 32 + lane;
        #pragma unroll 2
        for (int i = 0; i < 16; i++) {
            const float4 a0 = *(const float4*)(sat + i * 20);
            const float4 a1 = *(const float4*)(sat + i * 20 + 4);
            const float4 a2 = *(const float4*)(sat + i * 20 + 8);
            const float4 a3 = *(const float4*)(sat + i * 20 + 12);
            float gv = a0.x*hp[0] + a0.y*hp[1] + a0.z*hp[2] + a0.w*hp[3]
                     + a1.x*hp[4] + a1.y*hp[5] + a1.z*hp[6] + a1.w*hp[7]
                     + a2.x*hp[8] + a2.y*hp[9] + a2.z*hp[10]+ a2.w*hp[11]
                     + a3.x*hp[12]+ a3.y*hp[13]+ a3.z*hp[14]+ a3.w*hp[15];
            gv = gv > 0.f ? gv : expm1f(gv);     // elu
            gbase[i * 32] = gv;
        }
        __syncwarp();                            // sat reused next head
    }
}

// =========================== Kernel B: fused mixer v4 (FFMA2) ===============
// 16 rows/block, 256 blocks, 512 threads, 2 CTAs/SM.
// smem floats: sT(2064) sqs(256) Wc(4x4096=16384) w1acc(8448) = 108608 B
#define SMEM_B_FLOATS (2064 + 256 + 16384 + 8448)

__device__ __forceinline__ void cp_async16(float* s, const float* g) {
    unsigned a = (unsigned)__cvta_generic_to_shared(s);
    asm volatile("cp.async.cg.shared.global [%0], [%1], 16;" :: "r"(a), "l"(g));
}

__global__ __launch_bounds__(512, 2)
void mix_kernel(const float* __restrict__ qs_g,
                const float* __restrict__ s_g,
                const float* __restrict__ unc_g,
                const float* __restrict__ w1sW,
                const float* __restrict__ w1sb,
                float* __restrict__ out)
{
    extern __shared__ float sm[];
    float* sT    = sm;               // [129][16]  s_aug transposed
    float* sqs   = sT + 2064;        // [16][16]
    float* Wc    = sqs + 256;        // ring: 4 x [4][1024]
    float* w1acc = Wc + 16384;       // [256][33]

    const int tid  = threadIdx.x;
    const int brow = blockIdx.x * 16;
    const int lane = tid & 31;

    for (int idx = tid; idx < 2048; idx += 512) {
        int r = idx >> 7, k = idx & 127;
        sT[k * 16 + r] = s_g[(size_t)(brow + r) * 128 + k];
    }
    if (tid < 16) sT[128 * 16 + tid] = unc_g[brow + tid];
    if (tid < 256) {
        int r = tid >> 4, n = tid & 15;
        sqs[tid] = qs_g[(size_t)(brow + r) * 16 + n];
    }
    for (int idx = tid; idx < 8448; idx += 512) w1acc[idx] = 0.f;
    __syncthreads();

    const int colg = tid & 127;      // 128 column-groups
    const int rowg = tid >> 7;       // 4 row-groups of 4
    const int cA   = colg * 4;       // cols cA..+3 and 512+cA..+3
    const int r0   = rowg * 4;
    const int e0   = colg >> 3;
    const int d0   = (colg & 7) * 4;

    const int kk0 = tid >> 8,           cc0 = (tid & 255) * 4;
    const int kk1 = (tid + 512) >> 8,   cc1 = ((tid + 512) & 255) * 4;

    for (int h = 0; h < 4; h++) {
        const float* Wh = w1sW + h * 1024;

        #pragma unroll
        for (int c = 0; c < 3; c++) {
            float* dst = Wc + (c & 3) * 4096;
            const float* src = Wh + (size_t)c * 4 * 4096;
            cp_async16(dst + kk0 * 1024 + cc0, src + (size_t)kk0 * 4096 + cc0);
            cp_async16(dst + kk1 * 1024 + cc1, src + (size_t)kk1 * 4096 + cc1);
            asm volatile("cp.async.commit_group;");
        }

        // packed accumulators: acc[i][p] = cols {cA+2p, cA+2p+1} (p=0,1)
        //                                  {512+cA+2(p-2), ...}  (p=2,3)
        u64t acc[4][4];
        #pragma unroll
        for (int i = 0; i < 4; i++)
            #pragma unroll
            for (int p = 0; p < 4; p++) acc[i][p] = 0ull;

        #pragma unroll 1
        for (int kb = 0; kb < 32; kb++) {
            if (kb < 30) asm volatile("cp.async.wait_group 2;");
            else         asm volatile("cp.async.wait_group 0;");
            __syncthreads();

            if (kb + 3 < 32) {
                float* dst = Wc + ((kb + 3) & 3) * 4096;
                const float* src = Wh + (size_t)(kb + 3) * 4 * 4096;
                cp_async16(dst + kk0 * 1024 + cc0, src + (size_t)kk0 * 4096 + cc0);
                cp_async16(dst + kk1 * 1024 + cc1, src + (size_t)kk1 * 4096 + cc1);
                asm volatile("cp.async.commit_group;");
            }

            const float* W = Wc + (kb & 3) * 4096;
            const float* sTk = sT + kb * 4 * 16;
            #pragma unroll
            for (int kk = 0; kk < 4; kk++) {
                const float4 sa = *(const float4*)(sTk + kk * 16 + r0);
                const ulonglong2 wA = *(const ulonglong2*)(W + kk * 1024 + cA);
                const ulonglong2 wB = *(const ulonglong2*)(W + kk * 1024 + 512 + cA);
                const float sr[4] = {sa.x, sa.y, sa.z, sa.w};
                #pragma unroll
                for (int i = 0; i < 4; i++) {
                    const u64t sp = pack2(sr[i], sr[i]);
                    acc[i][0] = fma2(sp, wA.x, acc[i][0]);
                    acc[i][1] = fma2(sp, wA.y, acc[i][1]);
                    acc[i][2] = fma2(sp, wB.x, acc[i][2]);
                    acc[i][3] = fma2(sp, wB.y, acc[i][3]);
                }
            }
        }

        // tail: K row 128 (uncertainty) rank-1 + bias (scalar, unpacked)
        float av[4][8];
        {
            const float4 w0 = __ldg((const float4*)(w1sW + (size_t)128 * 4096 + h * 1024 + cA));
            const float4 w1 = __ldg((const float4*)(w1sW + (size_t)128 * 4096 + h * 1024 + 512 + cA));
            const float4 b0 = __ldg((const float4*)(w1sb + h * 1024 + cA));
            const float4 b1 = __ldg((const float4*)(w1sb + h * 1024 + 512 + cA));
            #pragma unroll
            for (int i = 0; i < 4; i++) {
                #pragma unroll
                for (int p = 0; p < 4; p++)
                    unpack2(acc[i][p], av[i][2 * p], av[i][2 * p + 1]);
                const float su = sT[128 * 16 + r0 + i];
                av[i][0] += su * w0.x + b0.x; av[i][1] += su * w0.y + b0.y;
                av[i][2] += su * w0.z + b0.z; av[i][3] += su * w0.w + b0.w;
                av[i][4] += su * w1.x + b1.x; av[i][5] += su * w1.y + b1.y;
                av[i][6] += su * w1.z + b1.z; av[i][7] += su * w1.w + b1.w;
            }
        }
        // repack for the contraction dot products
        u64t ap[4][4];
        #pragma unroll
        for (int i = 0; i < 4; i++)
            #pragma unroll
            for (int p = 0; p < 4; p++)
                ap[i][p] = pack2(av[i][2 * p], av[i][2 * p + 1]);

        // contraction: w1acc[r][n][e] += |sum_d ws[r][e*32+d] g[r][n][d]|
        for (int n = 0; n < 16; n++) {
            #pragma unroll
            for (int i = 0; i < 4; i++) {
                const ulonglong2 gp = *(const ulonglong2*)(
                    g_buf + (((size_t)(brow + r0 + i) * 4 + h) * 16 + n) * 32 + d0);
                u64t q0 = mul2(ap[i][0], gp.x); q0 = fma2(ap[i][1], gp.y, q0);
                u64t q1 = mul2(ap[i][2], gp.x); q1 = fma2(ap[i][3], gp.y, q1);
                float a0, a1, b0, b1;
                unpack2(q0, a0, a1); unpack2(q1, b0, b1);
                float p0 = a0 + a1, p1 = b0 + b1;
                p0 += __shfl_xor_sync(0xffffffffu, p0, 1);
                p1 += __shfl_xor_sync(0xffffffffu, p1, 1);
                p0 += __shfl_xor_sync(0xffffffffu, p0, 2);
                p1 += __shfl_xor_sync(0xffffffffu, p1, 2);
                p0 += __shfl_xor_sync(0xffffffffu, p0, 4);
                p1 += __shfl_xor_sync(0xffffffffu, p1, 4);
                if ((lane & 7) == 0) {
                    float* wa = w1acc + ((r0 + i) * 16 + n) * 33;
                    wa[e0]      += fabsf(p0);
                    wa[e0 + 16] += fabsf(p1);
                }
            }
        }
    }
    __syncthreads();

    // ---- epilogue: warp = row (16 warps), lane = e (EMB=32) ----
    {
        const int r = tid >> 5, e = lane;
        if (r < 16) {
            float ha = 0.f;
            #pragma unroll
            for (int n = 0; n < 16; n++)
                ha += sqs[r * 16 + n] * w1acc[(r * 16 + n) * 33 + e];
            const size_t eb = (size_t)(brow + r) * 65;
            float hid = 0.25f * ha + epi_buf[eb + e];
            hid = hid > 0.f ? hid : expm1f(hid);      // elu
            float ys = hid * epi_buf[eb + 32 + e];
            #pragma unroll
            for (int d = 16; d; d >>= 1)
                ys += __shfl_xor_sync(0xffffffffu, ys, d);
            if (e == 0)
                out[brow + r] = ys + epi_buf[eb + 64];
        }
    }
}

// =============================================================================
extern "C" void kernel_launch(void* const* d_in, const int* in_sizes, int n_in,
                              void* d_out, int out_size)
{
    const float* qs   = (const float*)d_in[0];
    const float* st   = (const float*)d_in[1];
    const float* hs   = (const float*)d_in[2];
    const float* unc  = (const float*)d_in[3];
    const float* Wg   = (const float*)d_in[4];
    const float* att  = (const float*)d_in[5];
    const float* w1sW = (const float*)d_in[6];
    const float* w1sb = (const float*)d_in[7];
    const float* b1W  = (const float*)d_in[8];
    const float* b1b  = (const float*)d_in[9];
    const float* wfW  = (const float*)d_in[10];
    const float* wfb  = (const float*)d_in[11];
    const float* V1W  = (const float*)d_in[12];
    const float* V1b  = (const float*)d_in[13];
    const float* V2W  = (const float*)d_in[14];
    const float* V2b  = (const float*)d_in[15];
    float* out = (float*)d_out;

    (void)in_sizes; (void)n_in; (void)out_size;

    cudaFuncSetAttribute(gat_kernel, cudaFuncAttributeMaxDynamicSharedMemorySize,
                         GAT_SMEM_FLOATS * sizeof(float));
    cudaFuncSetAttribute(mix_kernel, cudaFuncAttributeMaxDynamicSharedMemorySize,
                         SMEM_B_FLOATS * sizeof(float));

    gat_kernel<<<512, 256, GAT_SMEM_FLOATS * sizeof(float)>>>(
        hs, Wg, att, st, b1W, b1b, wfW, wfb, V1W, V1b, V2W, V2b);
    mix_kernel<<<256, 512, SMEM_B_FLOATS * sizeof(float)>>>(
        qs, st, unc, w1sW, w1sb, out);
}

// round 5
// speedup vs baseline: 1.0041x; 1.0041x over previous
#include <cuda_runtime.h>
#include <cuda_bf16.h>
#include <math.h>

// ---------------------------------------------------------------------------
// DVDMixer: B = 32*128 = 4096 rows
// N_AGENTS=16, RNN_H=64, N_HEADS=4, GAT_D=32, EMB=32, SDIM=128
// ---------------------------------------------------------------------------

#define BROWS 4096

__device__ float g_buf[(size_t)BROWS * 4 * 16 * 32];   // 33.5 MB (L2-resident)
__device__ float epi_buf[(size_t)BROWS * 65];          // b1v | |wf| | v

// ---------------- packed fp32x2 helpers (FFMA2 — PTX-only on sm_103a) -------
typedef unsigned long long u64t;
__device__ __forceinline__ u64t pack2(float lo, float hi) {
    u64t r; asm("mov.b64 %0,{%1,%2};" : "=l"(r) : "f"(lo), "f"(hi)); return r;
}
__device__ __forceinline__ void unpack2(u64t v, float& lo, float& hi) {
    asm("mov.b64 {%0,%1},%2;" : "=f"(lo), "=f"(hi) : "l"(v));
}
__device__ __forceinline__ u64t fma2(u64t a, u64t b, u64t c) {
    u64t d; asm("fma.rn.f32x2 %0,%1,%2,%3;" : "=l"(d) : "l"(a), "l"(b), "l"(c));
    return d;
}
__device__ __forceinline__ u64t mul2(u64t a, u64t b) {
    u64t d; asm("mul.rn.f32x2 %0,%1,%2;" : "=l"(d) : "l"(a), "l"(b));
    return d;
}

// ============================= Kernel A: GAT + epilogue prep ================
// 8 rows/block (1 warp per row), 256 threads, 512 blocks, 2 CTAs/SM (128 regs).
#define GAT_SMEM_FLOATS (8192 + 2560)

__global__ __launch_bounds__(256, 2)
void gat_kernel(const float* __restrict__ hs_g,
                const float* __restrict__ Wg,
                const float* __restrict__ att,
                const float* __restrict__ s_g,
                const float* __restrict__ b1W, const float* __restrict__ b1b,
                const float* __restrict__ wfW, const float* __restrict__ wfb,
                const float* __restrict__ V1W, const float* __restrict__ V1b,
                const float* __restrict__ V2W, const float* __restrict__ V2b)
{
    extern __shared__ float sm[];
    float* shs   = sm;            // [8][16][64]
    float* sattn = sm + 8192;     // [8][16][20]

    const int tid  = threadIdx.x;
    const int lane = tid & 31;
    const int w    = tid >> 5;     // warp = local row
    const int brow = blockIdx.x * 8;

    // stage hs (coalesced float4)
    const float4* src4 = (const float4*)(hs_g + (size_t)brow * 1024);
    for (int i = tid; i < 2048; i += 256)
        ((float4*)shs)[i] = src4[i];

    // ---- epilogue prep for row (brow+w): lane = e (EMB=32) ----
    {
        const int row = brow + w;
        float ab = 0.f, aw = 0.f, av = 0.f;
        const float* srow = s_g + (size_t)row * 128;
        #pragma unroll 4
        for (int k = 0; k < 128; k++) {
            const float sv = __ldg(srow + k);
            ab += sv * __ldg(b1W + k * 32 + lane);
            aw += sv * __ldg(wfW + k * 32 + lane);
            av += sv * __ldg(V1W + k * 32 + lane);
        }
        const float b1v = ab + __ldg(b1b + lane);
        const float wfv = fabsf(aw + __ldg(wfb + lane));
        float v1 = fmaxf(av + __ldg(V1b + lane), 0.f) * __ldg(V2W + lane);
        #pragma unroll
        for (int d = 16; d; d >>= 1)
            v1 += __shfl_xor_sync(0xffffffffu, v1, d);
        epi_buf[(size_t)row * 65 + lane]      = b1v;
        epi_buf[(size_t)row * 65 + 32 + lane] = wfv;
        if (lane == 0)
            epi_buf[(size_t)row * 65 + 64] = v1 + __ldg(V2b);
    }
    __syncthreads();

    // ---- GAT per head, hp register-resident (lane = d, 32 dims) ----
    float* sat = sattn + w * 320;             // [16][20]
    const float* hsrow = shs + w * 1024;      // [16][64]

    for (int h = 0; h < 4; h++) {
        float hp[16];
        #pragma unroll
        for (int n = 0; n < 16; n++) hp[n] = 0.f;

        const float* Wcol = Wg + h * 32 + lane;
        #pragma unroll 4
        for (int kq = 0; kq < 16; kq++) {
            const float w0 = __ldg(Wcol + (4 * kq + 0) * 128);
            const float w1 = __ldg(Wcol + (4 * kq + 1) * 128);
            const float w2 = __ldg(Wcol + (4 * kq + 2) * 128);
            const float w3 = __ldg(Wcol + (4 * kq + 3) * 128);
            #pragma unroll
            for (int n = 0; n < 16; n++) {
                const float4 hv = *(const float4*)(hsrow + n * 64 + kq * 4);
                hp[n] += hv.x * w0 + hv.y * w1 + hv.z * w2 + hv.w * w3;
            }
        }

        // src/dst via butterfly reductions over d (=lanes)
        const float asrc = __ldg(att + h * 64 + lane);
        const float adst = __ldg(att + h * 64 + 32 + lane);
        float srcv[16], dstv[16];
        #pragma unroll
        for (int n = 0; n < 16; n++) {
            float ps = hp[n] * asrc, pd = hp[n] * adst;
            #pragma unroll
            for (int d = 16; d; d >>= 1) {
                ps += __shfl_xor_sync(0xffffffffu, ps, d);
                pd += __shfl_xor_sync(0xffffffffu, pd, d);
            }
            srcv[n] = ps; dstv[n] = pd;
        }

        // softmax: lane handles (i = lane&15, j in (lane>>4)*8 .. +8)
        {
            const int i  = lane & 15;
            const int jb = (lane >> 4) * 8;
            float e[8], mx = -1e30f;
            #pragma unroll
            for (int jj = 0; jj < 8; jj++) {
                float x = srcv[i] + dstv[jb + jj];
                x = x > 0.f ? x : 0.2f * x;      // leaky_relu 0.2
                e[jj] = x;
                mx = fmaxf(mx, x);
            }
            mx = fmaxf(mx, __shfl_xor_sync(0xffffffffu, mx, 16));
            float s = 0.f;
            #pragma unroll
            for (int jj = 0; jj < 8; jj++) { e[jj] = expf(e[jj] - mx); s += e[jj]; }
            s += __shfl_xor_sync(0xffffffffu, s, 16);
            const float inv = 1.f / s;
            #pragma unroll
            for (int jj = 0; jj < 8; jj++)
                sat[i * 20 + jb + jj] = e[jj] * inv;
        }
        __syncwarp();

        // g[i][d] = elu( sum_j attn[i][j] * hp[j][d] ), lane = d
        float* gbase = g_buf + (((size_t)(brow + w) * 4 + h) * 16) * 32 + lane;
        #pragma unroll 2
        for (int i = 0; i < 16; i++) {
            const float4 a0 = *(const float4*)(sat + i * 20);
            const float4 a1 = *(const float4*)(sat + i * 20 + 4);
            const float4 a2 = *(const float4*)(sat + i * 20 + 8);
            const float4 a3 = *(const float4*)(sat + i * 20 + 12);
            float gv = a0.x*hp[0] + a0.y*hp[1] + a0.z*hp[2] + a0.w*hp[3]
                     + a1.x*hp[4] + a1.y*hp[5] + a1.z*hp[6] + a1.w*hp[7]
                     + a2.x*hp[8] + a2.y*hp[9] + a2.z*hp[10]+ a2.w*hp[11]
                     + a3.x*hp[12]+ a3.y*hp[13]+ a3.z*hp[14]+ a3.w*hp[15];
            gv = gv > 0.f ? gv : expm1f(gv);     // elu
            gbase[i * 32] = gv;
        }
        __syncwarp();                            // sat reused next head
    }
}

// =========================== Kernel B: fused mixer v4 (FFMA2) ===============
// 16 rows/block, 256 blocks, 512 threads, 2 CTAs/SM.
// smem floats: sT(2064) sqs(256) Wc(4x4096=16384) w1acc(8448) = 108608 B
#define SMEM_B_FLOATS (2064 + 256 + 16384 + 8448)

__device__ __forceinline__ void cp_async16(float* s, const float* g) {
    unsigned a = (unsigned)__cvta_generic_to_shared(s);
    asm volatile("cp.async.cg.shared.global [%0], [%1], 16;" :: "r"(a), "l"(g));
}

__global__ __launch_bounds__(512, 2)
void mix_kernel(const float* __restrict__ qs_g,
                const float* __restrict__ s_g,
                const float* __restrict__ unc_g,
                const float* __restrict__ w1sW,
                const float* __restrict__ w1sb,
                float* __restrict__ out)
{
    extern __shared__ float sm[];
    float* sT    = sm;               // [129][16]  s_aug transposed
    float* sqs   = sT + 2064;        // [16][16]
    float* Wc    = sqs + 256;        // ring: 4 x [4][1024]
    float* w1acc = Wc + 16384;       // [256][33]

    const int tid  = threadIdx.x;
    const int brow = blockIdx.x * 16;
    const int lane = tid & 31;

    for (int idx = tid; idx < 2048; idx += 512) {
        int r = idx >> 7, k = idx & 127;
        sT[k * 16 + r] = s_g[(size_t)(brow + r) * 128 + k];
    }
    if (tid < 16) sT[128 * 16 + tid] = unc_g[brow + tid];
    if (tid < 256) {
        int r = tid >> 4, n = tid & 15;
        sqs[tid] = qs_g[(size_t)(brow + r) * 16 + n];
    }
    for (int idx = tid; idx < 8448; idx += 512) w1acc[idx] = 0.f;
    __syncthreads();

    const int colg = tid & 127;      // 128 column-groups
    const int rowg = tid >> 7;       // 4 row-groups of 4
    const int cA   = colg * 4;       // cols cA..+3 and 512+cA..+3
    const int r0   = rowg * 4;
    const int e0   = colg >> 3;
    const int d0   = (colg & 7) * 4;

    const int kk0 = tid >> 8,           cc0 = (tid & 255) * 4;
    const int kk1 = (tid + 512) >> 8,   cc1 = ((tid + 512) & 255) * 4;

    for (int h = 0; h < 4; h++) {
        const float* Wh = w1sW + h * 1024;

        #pragma unroll
        for (int c = 0; c < 3; c++) {
            float* dst = Wc + (c & 3) * 4096;
            const float* src = Wh + (size_t)c * 4 * 4096;
            cp_async16(dst + kk0 * 1024 + cc0, src + (size_t)kk0 * 4096 + cc0);
            cp_async16(dst + kk1 * 1024 + cc1, src + (size_t)kk1 * 4096 + cc1);
            asm volatile("cp.async.commit_group;");
        }

        // packed accumulators: acc[i][p] = cols {cA+2p, cA+2p+1} (p=0,1)
        //                                  {512+cA+2(p-2), ...}  (p=2,3)
        u64t acc[4][4];
        #pragma unroll
        for (int i = 0; i < 4; i++)
            #pragma unroll
            for (int p = 0; p < 4; p++) acc[i][p] = 0ull;

        #pragma unroll 1
        for (int kb = 0; kb < 32; kb++) {
            if (kb < 30) asm volatile("cp.async.wait_group 2;");
            else         asm volatile("cp.async.wait_group 0;");
            __syncthreads();

            if (kb + 3 < 32) {
                float* dst = Wc + ((kb + 3) & 3) * 4096;
                const float* src = Wh + (size_t)(kb + 3) * 4 * 4096;
                cp_async16(dst + kk0 * 1024 + cc0, src + (size_t)kk0 * 4096 + cc0);
                cp_async16(dst + kk1 * 1024 + cc1, src + (size_t)kk1 * 4096 + cc1);
                asm volatile("cp.async.commit_group;");
            }

            const float* W = Wc + (kb & 3) * 4096;
            const float* sTk = sT + kb * 4 * 16;
            #pragma unroll
            for (int kk = 0; kk < 4; kk++) {
                const float4 sa = *(const float4*)(sTk + kk * 16 + r0);
                const ulonglong2 wA = *(const ulonglong2*)(W + kk * 1024 + cA);
                const ulonglong2 wB = *(const ulonglong2*)(W + kk * 1024 + 512 + cA);
                const float sr[4] = {sa.x, sa.y, sa.z, sa.w};
                #pragma unroll
                for (int i = 0; i < 4; i++) {
                    const u64t sp = pack2(sr[i], sr[i]);
                    acc[i][0] = fma2(sp, wA.x, acc[i][0]);
                    acc[i][1] = fma2(sp, wA.y, acc[i][1]);
                    acc[i][2] = fma2(sp, wB.x, acc[i][2]);
                    acc[i][3] = fma2(sp, wB.y, acc[i][3]);
                }
            }
        }

        // tail: K row 128 (uncertainty) rank-1 + bias (scalar, unpacked)
        float av[4][8];
        {
            const float4 w0 = __ldg((const float4*)(w1sW + (size_t)128 * 4096 + h * 1024 + cA));
            const float4 w1 = __ldg((const float4*)(w1sW + (size_t)128 * 4096 + h * 1024 + 512 + cA));
            const float4 b0 = __ldg((const float4*)(w1sb + h * 1024 + cA));
            const float4 b1 = __ldg((const float4*)(w1sb + h * 1024 + 512 + cA));
            #pragma unroll
            for (int i = 0; i < 4; i++) {
                #pragma unroll
                for (int p = 0; p < 4; p++)
                    unpack2(acc[i][p], av[i][2 * p], av[i][2 * p + 1]);
                const float su = sT[128 * 16 + r0 + i];
                av[i][0] += su * w0.x + b0.x; av[i][1] += su * w0.y + b0.y;
                av[i][2] += su * w0.z + b0.z; av[i][3] += su * w0.w + b0.w;
                av[i][4] += su * w1.x + b1.x; av[i][5] += su * w1.y + b1.y;
                av[i][6] += su * w1.z + b1.z; av[i][7] += su * w1.w + b1.w;
            }
        }
        // repack for the contraction dot products
        u64t ap[4][4];
        #pragma unroll
        for (int i = 0; i < 4; i++)
            #pragma unroll
            for (int p = 0; p < 4; p++)
                ap[i][p] = pack2(av[i][2 * p], av[i][2 * p + 1]);

        // contraction: w1acc[r][n][e] += |sum_d ws[r][e*32+d] g[r][n][d]|
        for (int n = 0; n < 16; n++) {
            #pragma unroll
            for (int i = 0; i < 4; i++) {
                const ulonglong2 gp = *(const ulonglong2*)(
                    g_buf + (((size_t)(brow + r0 + i) * 4 + h) * 16 + n) * 32 + d0);
                u64t q0 = mul2(ap[i][0], gp.x); q0 = fma2(ap[i][1], gp.y, q0);
                u64t q1 = mul2(ap[i][2], gp.x); q1 = fma2(ap[i][3], gp.y, q1);
                float a0, a1, b0, b1;
                unpack2(q0, a0, a1); unpack2(q1, b0, b1);
                float p0 = a0 + a1, p1 = b0 + b1;
                p0 += __shfl_xor_sync(0xffffffffu, p0, 1);
                p1 += __shfl_xor_sync(0xffffffffu, p1, 1);
                p0 += __shfl_xor_sync(0xffffffffu, p0, 2);
                p1 += __shfl_xor_sync(0xffffffffu, p1, 2);
                p0 += __shfl_xor_sync(0xffffffffu, p0, 4);
                p1 += __shfl_xor_sync(0xffffffffu, p1, 4);
                if ((lane & 7) == 0) {
                    float* wa = w1acc + ((r0 + i) * 16 + n) * 33;
                    wa[e0]      += fabsf(p0);
                    wa[e0 + 16] += fabsf(p1);
                }
            }
        }
    }
    __syncthreads();

    // ---- epilogue: warp = row (16 warps), lane = e (EMB=32) ----
    {
        const int r = tid >> 5, e = lane;
        if (r < 16) {
            float ha = 0.f;
            #pragma unroll
            for (int n = 0; n < 16; n++)
                ha += sqs[r * 16 + n] * w1acc[(r * 16 + n) * 33 + e];
            const size_t eb = (size_t)(brow + r) * 65;
            float hid = 0.25f * ha + epi_buf[eb + e];
            hid = hid > 0.f ? hid : expm1f(hid);      // elu
            float ys = hid * epi_buf[eb + 32 + e];
            #pragma unroll
            for (int d = 16; d; d >>= 1)
                ys += __shfl_xor_sync(0xffffffffu, ys, d);
            if (e == 0)
                out[brow + r] = ys + epi_buf[eb + 64];
        }
    }
}

// =============================================================================
extern "C" void kernel_launch(void* const* d_in, const int* in_sizes, int n_in,
                              void* d_out, int out_size)
{
    const float* qs   = (const float*)d_in[0];
    const float* st   = (const float*)d_in[1];
    const float* hs   = (const float*)d_in[2];
    const float* unc  = (const float*)d_in[3];
    const float* Wg   = (const float*)d_in[4];
    const float* att  = (const float*)d_in[5];
    const float* w1sW = (const float*)d_in[6];
    const float* w1sb = (const float*)d_in[7];
    const float* b1W  = (const float*)d_in[8];
    const float* b1b  = (const float*)d_in[9];
    const float* wfW  = (const float*)d_in[10];
    const float* wfb  = (const float*)d_in[11];
    const float* V1W  = (const float*)d_in[12];
    const float* V1b  = (const float*)d_in[13];
    const float* V2W  = (const float*)d_in[14];
    const float* V2b  = (const float*)d_in[15];
    float* out = (float*)d_out;

    (void)in_sizes; (void)n_in; (void)out_size;

    cudaFuncSetAttribute(gat_kernel, cudaFuncAttributeMaxDynamicSharedMemorySize,
                         GAT_SMEM_FLOATS * sizeof(float));
    cudaFuncSetAttribute(mix_kernel, cudaFuncAttributeMaxDynamicSharedMemorySize,
                         SMEM_B_FLOATS * sizeof(float));

    gat_kernel<<<512, 256, GAT_SMEM_FLOATS * sizeof(float)>>>(
        hs, Wg, att, st, b1W, b1b, wfW, wfb, V1W, V1b, V2W, V2b);
    mix_kernel<<<256, 512, SMEM_B_FLOATS * sizeof(float)>>>(
        qs, st, unc, w1sW, w1sb, out);
}

// round 10
// speedup vs baseline: 1.0593x; 1.0549x over previous
#include <cuda_runtime.h>
#include <cuda_bf16.h>
#include <math.h>

// ---------------------------------------------------------------------------
// DVDMixer: B = 32*128 = 4096 rows
// N_AGENTS=16, RNN_H=64, N_HEADS=4, GAT_D=32, EMB=32, SDIM=128
// fp32 CUDA-core implementation (tcgen05 not reachable through this harness
// toolchain — plain sm_103 ptxas pass; three rounds of evidence, R6-R9).
// ---------------------------------------------------------------------------

#define BROWS 4096

__device__ float g_buf[(size_t)BROWS * 4 * 16 * 32];   // 33.5 MB (L2-resident)
__device__ float epi_buf[(size_t)BROWS * 65];          // b1v | |wf| | v

// fast exp: MUFU-based, rel err ~2^-21 (threshold is 1e-3; we pass at ~1e-7)
__device__ __forceinline__ float fexp(float x) { return __expf(x); }
__device__ __forceinline__ float felu(float x) {
    return x > 0.f ? x : (__expf(x) - 1.f);
}

// ============================= Kernel A: GAT + epilogue prep ================
// 8 rows/block (1 warp per row), 256 threads, 512 blocks, 2 CTAs/SM.
#define GAT_SMEM_FLOATS (8192 + 2560)

__global__ __launch_bounds__(256, 2)
void gat_kernel(const float* __restrict__ hs_g,
                const float* __restrict__ Wg,
                const float* __restrict__ att,
                const float* __restrict__ s_g,
                const float* __restrict__ b1W, const float* __restrict__ b1b,
                const float* __restrict__ wfW, const float* __restrict__ wfb,
                const float* __restrict__ V1W, const float* __restrict__ V1b,
                const float* __restrict__ V2W, const float* __restrict__ V2b)
{
    extern __shared__ float sm[];
    float* shs   = sm;            // [8][16][64]
    float* sattn = sm + 8192;     // [8][16][20]

    const int tid  = threadIdx.x;
    const int lane = tid & 31;
    const int w    = tid >> 5;     // warp = local row
    const int brow = blockIdx.x * 8;

    // stage hs (coalesced float4)
    const float4* src4 = (const float4*)(hs_g + (size_t)brow * 1024);
    for (int i = tid; i < 2048; i += 256)
        ((float4*)shs)[i] = src4[i];

    // ---- epilogue prep for row (brow+w): lane = e (EMB=32) ----
    {
        const int row = brow + w;
        float ab = 0.f, aw = 0.f, av = 0.f;
        const float* srow = s_g + (size_t)row * 128;
        #pragma unroll 4
        for (int k = 0; k < 128; k++) {
            const float sv = __ldg(srow + k);
            ab += sv * __ldg(b1W + k * 32 + lane);
            aw += sv * __ldg(wfW + k * 32 + lane);
            av += sv * __ldg(V1W + k * 32 + lane);
        }
        const float b1v = ab + __ldg(b1b + lane);
        const float wfv = fabsf(aw + __ldg(wfb + lane));
        float v1 = fmaxf(av + __ldg(V1b + lane), 0.f) * __ldg(V2W + lane);
        #pragma unroll
        for (int d = 16; d; d >>= 1)
            v1 += __shfl_xor_sync(0xffffffffu, v1, d);
        epi_buf[(size_t)row * 65 + lane]      = b1v;
        epi_buf[(size_t)row * 65 + 32 + lane] = wfv;
        if (lane == 0)
            epi_buf[(size_t)row * 65 + 64] = v1 + __ldg(V2b);
    }
    __syncthreads();

    // ---- GAT per head, hp register-resident (lane = d, 32 dims) ----
    float* sat = sattn + w * 320;             // [16][20]
    const float* hsrow = shs + w * 1024;      // [16][64]

    for (int h = 0; h < 4; h++) {
        float hp[16];
        #pragma unroll
        for (int n = 0; n < 16; n++) hp[n] = 0.f;

        const float* Wcol = Wg + h * 32 + lane;
        #pragma unroll 4
        for (int kq = 0; kq < 16; kq++) {
            const float w0 = __ldg(Wcol + (4 * kq + 0) * 128);
            const float w1 = __ldg(Wcol + (4 * kq + 1) * 128);
            const float w2 = __ldg(Wcol + (4 * kq + 2) * 128);
            const float w3 = __ldg(Wcol + (4 * kq + 3) * 128);
            #pragma unroll
            for (int n = 0; n < 16; n++) {
                const float4 hv = *(const float4*)(hsrow + n * 64 + kq * 4);
                hp[n] += hv.x * w0 + hv.y * w1 + hv.z * w2 + hv.w * w3;
            }
        }

        // src/dst via butterfly reductions over d (=lanes)
        const float asrc = __ldg(att + h * 64 + lane);
        const float adst = __ldg(att + h * 64 + 32 + lane);
        float srcv[16], dstv[16];
        #pragma unroll
        for (int n = 0; n < 16; n++) {
            float ps = hp[n] * asrc, pd = hp[n] * adst;
            #pragma unroll
            for (int d = 16; d; d >>= 1) {
                ps += __shfl_xor_sync(0xffffffffu, ps, d);
                pd += __shfl_xor_sync(0xffffffffu, pd, d);
            }
            srcv[n] = ps; dstv[n] = pd;
        }

        // softmax: lane handles (i = lane&15, j in (lane>>4)*8 .. +8)
        {
            const int i  = lane & 15;
            const int jb = (lane >> 4) * 8;
            float e[8], mx = -1e30f;
            #pragma unroll
            for (int jj = 0; jj < 8; jj++) {
                float x = srcv[i] + dstv[jb + jj];
                x = x > 0.f ? x : 0.2f * x;      // leaky_relu 0.2
                e[jj] = x;
                mx = fmaxf(mx, x);
            }
            mx = fmaxf(mx, __shfl_xor_sync(0xffffffffu, mx, 16));
            float s = 0.f;
            #pragma unroll
            for (int jj = 0; jj < 8; jj++) { e[jj] = fexp(e[jj] - mx); s += e[jj]; }
            s += __shfl_xor_sync(0xffffffffu, s, 16);
            const float inv = 1.f / s;
            #pragma unroll
            for (int jj = 0; jj < 8; jj++)
                sat[i * 20 + jb + jj] = e[jj] * inv;
        }
        __syncwarp();

        // g[i][d] = elu( sum_j attn[i][j] * hp[j][d] ), lane = d
        float* gbase = g_buf + (((size_t)(brow + w) * 4 + h) * 16) * 32 + lane;
        #pragma unroll 2
        for (int i = 0; i < 16; i++) {
            const float4 a0 = *(const float4*)(sat + i * 20);
            const float4 a1 = *(const float4*)(sat + i * 20 + 4);
            const float4 a2 = *(const float4*)(sat + i * 20 + 8);
            const float4 a3 = *(const float4*)(sat + i * 20 + 12);
            float gv = a0.x*hp[0] + a0.y*hp[1] + a0.z*hp[2] + a0.w*hp[3]
                     + a1.x*hp[4] + a1.y*hp[5] + a1.z*hp[6] + a1.w*hp[7]
                     + a2.x*hp[8] + a2.y*hp[9] + a2.z*hp[10]+ a2.w*hp[11]
                     + a3.x*hp[12]+ a3.y*hp[13]+ a3.z*hp[14]+ a3.w*hp[15];
            gbase[i * 32] = felu(gv);
        }
        __syncwarp();                            // sat reused next head
    }
}

// =========================== Kernel B: fused mixer (R3, measured 208us) =====
// 16 rows/block, 256 blocks, 512 threads, 2 CTAs/SM.
#define SMEM_B_FLOATS (2064 + 256 + 16384 + 8448)

__device__ __forceinline__ void cp_async16(float* s, const float* g) {
    unsigned a = (unsigned)__cvta_generic_to_shared(s);
    asm volatile("cp.async.cg.shared.global [%0], [%1], 16;" :: "r"(a), "l"(g));
}

__global__ __launch_bounds__(512, 2)
void mix_kernel(const float* __restrict__ qs_g,
                const float* __restrict__ s_g,
                const float* __restrict__ unc_g,
                const float* __restrict__ w1sW,
                const float* __restrict__ w1sb,
                float* __restrict__ out)
{
    extern __shared__ float sm[];
    float* sT    = sm;               // [129][16]  s_aug transposed
    float* sqs   = sT + 2064;        // [16][16]
    float* Wc    = sqs + 256;        // ring: 4 x [4][1024]
    float* w1acc = Wc + 16384;       // [256][33]

    const int tid  = threadIdx.x;
    const int brow = blockIdx.x * 16;
    const int lane = tid & 31;

    for (int idx = tid; idx < 2048; idx += 512) {
        int r = idx >> 7, k = idx & 127;
        sT[k * 16 + r] = s_g[(size_t)(brow + r) * 128 + k];
    }
    if (tid < 16) sT[128 * 16 + tid] = unc_g[brow + tid];
    if (tid < 256) {
        int r = tid >> 4, n = tid & 15;
        sqs[tid] = qs_g[(size_t)(brow + r) * 16 + n];
    }
    for (int idx = tid; idx < 8448; idx += 512) w1acc[idx] = 0.f;
    __syncthreads();

    const int colg = tid & 127;      // 128 column-groups
    const int rowg = tid >> 7;       // 4 row-groups of 4
    const int cA   = colg * 4;       // cols cA..+3 and 512+cA..+3
    const int r0   = rowg * 4;
    const int e0   = colg >> 3;
    const int d0   = (colg & 7) * 4;

    const int kk0 = tid >> 8,           cc0 = (tid & 255) * 4;
    const int kk1 = (tid + 512) >> 8,   cc1 = ((tid + 512) & 255) * 4;

    for (int h = 0; h < 4; h++) {
        const float* Wh = w1sW + h * 1024;

        #pragma unroll
        for (int c = 0; c < 3; c++) {
            float* dst = Wc + (c & 3) * 4096;
            const float* src = Wh + (size_t)c * 4 * 4096;
            cp_async16(dst + kk0 * 1024 + cc0, src + (size_t)kk0 * 4096 + cc0);
            cp_async16(dst + kk1 * 1024 + cc1, src + (size_t)kk1 * 4096 + cc1);
            asm volatile("cp.async.commit_group;");
        }

        float acc[4][8];
        #pragma unroll
        for (int i = 0; i < 4; i++)
            #pragma unroll
            for (int j = 0; j < 8; j++) acc[i][j] = 0.f;

        #pragma unroll 1
        for (int kb = 0; kb < 32; kb++) {
            if (kb < 30) asm volatile("cp.async.wait_group 2;");
            else         asm volatile("cp.async.wait_group 0;");
            __syncthreads();

            if (kb + 3 < 32) {
                float* dst = Wc + ((kb + 3) & 3) * 4096;
                const float* src = Wh + (size_t)(kb + 3) * 4 * 4096;
                cp_async16(dst + kk0 * 1024 + cc0, src + (size_t)kk0 * 4096 + cc0);
                cp_async16(dst + kk1 * 1024 + cc1, src + (size_t)kk1 * 4096 + cc1);
                asm volatile("cp.async.commit_group;");
            }

            const float* W = Wc + (kb & 3) * 4096;
            const float* sTk = sT + kb * 4 * 16;
            #pragma unroll
            for (int kk = 0; kk < 4; kk++) {
                const float4 sa = *(const float4*)(sTk + kk * 16 + r0);
                const float4 w0 = *(const float4*)(W + kk * 1024 + cA);
                const float4 w1 = *(const float4*)(W + kk * 1024 + 512 + cA);
                const float sr[4] = {sa.x, sa.y, sa.z, sa.w};
                #pragma unroll
                for (int i = 0; i < 4; i++) {
                    acc[i][0] += sr[i] * w0.x; acc[i][1] += sr[i] * w0.y;
                    acc[i][2] += sr[i] * w0.z; acc[i][3] += sr[i] * w0.w;
                    acc[i][4] += sr[i] * w1.x; acc[i][5] += sr[i] * w1.y;
                    acc[i][6] += sr[i] * w1.z; acc[i][7] += sr[i] * w1.w;
                }
            }
        }

        // tail: K row 128 (uncertainty) rank-1 + bias
        {
            const float4 w0 = __ldg((const float4*)(w1sW + (size_t)128 * 4096 + h * 1024 + cA));
            const float4 w1 = __ldg((const float4*)(w1sW + (size_t)128 * 4096 + h * 1024 + 512 + cA));
            const float4 b0 = __ldg((const float4*)(w1sb + h * 1024 + cA));
            const float4 b1 = __ldg((const float4*)(w1sb + h * 1024 + 512 + cA));
            #pragma unroll
            for (int i = 0; i < 4; i++) {
                const float su = sT[128 * 16 + r0 + i];
                acc[i][0] += su * w0.x + b0.x; acc[i][1] += su * w0.y + b0.y;
                acc[i][2] += su * w0.z + b0.z; acc[i][3] += su * w0.w + b0.w;
                acc[i][4] += su * w1.x + b1.x; acc[i][5] += su * w1.y + b1.y;
                acc[i][6] += su * w1.z + b1.z; acc[i][7] += su * w1.w + b1.w;
            }
        }

        // contraction: w1acc[r][n][e] += |sum_d ws[r][e*32+d] g[r][n][d]|
        for (int n = 0; n < 16; n++) {
            #pragma unroll
            for (int i = 0; i < 4; i++) {
                const float4 gv = __ldg((const float4*)(
                    g_buf + (((size_t)(brow + r0 + i) * 4 + h) * 16 + n) * 32 + d0));
                float p0 = acc[i][0]*gv.x + acc[i][1]*gv.y + acc[i][2]*gv.z + acc[i][3]*gv.w;
                float p1 = acc[i][4]*gv.x + acc[i][5]*gv.y + acc[i][6]*gv.z + acc[i][7]*gv.w;
                p0 += __shfl_xor_sync(0xffffffffu, p0, 1);
                p1 += __shfl_xor_sync(0xffffffffu, p1, 1);
                p0 += __shfl_xor_sync(0xffffffffu, p0, 2);
                p1 += __shfl_xor_sync(0xffffffffu, p1, 2);
                p0 += __shfl_xor_sync(0xffffffffu, p0, 4);
                p1 += __shfl_xor_sync(0xffffffffu, p1, 4);
                if ((lane & 7) == 0) {
                    float* wa = w1acc + ((r0 + i) * 16 + n) * 33;
                    wa[e0]      += fabsf(p0);
                    wa[e0 + 16] += fabsf(p1);
                }
            }
        }
    }
    __syncthreads();

    // ---- epilogue: warp = row (16 warps), lane = e (EMB=32) ----
    {
        const int r = tid >> 5, e = lane;
        if (r < 16) {
            float ha = 0.f;
            #pragma unroll
            for (int n = 0; n < 16; n++)
                ha += sqs[r * 16 + n] * w1acc[(r * 16 + n) * 33 + e];
            const size_t eb = (size_t)(brow + r) * 65;
            float hid = felu(0.25f * ha + epi_buf[eb + e]);
            float ys = hid * epi_buf[eb + 32 + e];
            #pragma unroll
            for (int d = 16; d; d >>= 1)
                ys += __shfl_xor_sync(0xffffffffu, ys, d);
            if (e == 0)
                out[brow + r] = ys + epi_buf[eb + 64];
        }
    }
}

// =============================================================================
extern "C" void kernel_launch(void* const* d_in, const int* in_sizes, int n_in,
                              void* d_out, int out_size)
{
    const float* qs   = (const float*)d_in[0];
    const float* st   = (const float*)d_in[1];
    const float* hs   = (const float*)d_in[2];
    const float* unc  = (const float*)d_in[3];
    const float* Wg   = (const float*)d_in[4];
    const float* att  = (const float*)d_in[5];
    const float* w1sW = (const float*)d_in[6];
    const float* w1sb = (const float*)d_in[7];
    const float* b1W  = (const float*)d_in[8];
    const float* b1b  = (const float*)d_in[9];
    const float* wfW  = (const float*)d_in[10];
    const float* wfb  = (const float*)d_in[11];
    const float* V1W  = (const float*)d_in[12];
    const float* V1b  = (const float*)d_in[13];
    const float* V2W  = (const float*)d_in[14];
    const float* V2b  = (const float*)d_in[15];
    float* out = (float*)d_out;

    (void)in_sizes; (void)n_in; (void)out_size;

    cudaFuncSetAttribute(gat_kernel, cudaFuncAttributeMaxDynamicSharedMemorySize,
                         GAT_SMEM_FLOATS * sizeof(float));
    cudaFuncSetAttribute(mix_kernel, cudaFuncAttributeMaxDynamicSharedMemorySize,
                         SMEM_B_FLOATS * sizeof(float));

    gat_kernel<<<512, 256, GAT_SMEM_FLOATS * sizeof(float)>>>(
        hs, Wg, att, st, b1W, b1b, wfW, wfb, V1W, V1b, V2W, V2b);
    mix_kernel<<<256, 512, SMEM_B_FLOATS * sizeof(float)>>>(
        qs, st, unc, w1sW, w1sb, out);
}